// round 6
// baseline (speedup 1.0000x reference)
#include <cuda_runtime.h>
#include <cuda_bf16.h>
#include <math.h>

#define NUM_ENT 14541
#define EMBED_DIM 200
#define BATCH 256
#define GAMMA 9.0f

#define N_BTILE 4            // 256 / 64
#define N_NTILE 114          // ceil(14541 / 128)
#define NUM_TILES (N_BTILE * N_NTILE)   // 456
#define GRID_CTAS (148 * 3)  // 444: exactly 3 CTAs per SM

// Scratch for obj = ent[sub] + rel[rel]  (256 x 200 fp32 = 200 KB)
__device__ float g_obj[BATCH * EMBED_DIM];
__device__ unsigned int g_tile_counter;

__global__ void obj_kernel(const float* __restrict__ ent,
                           const float* __restrict__ relE,
                           const int* __restrict__ sub,
                           const int* __restrict__ rel) {
    if (blockIdx.x == 0 && threadIdx.x == 0) g_tile_counter = 0u;  // reset per launch
    int b = blockIdx.x;
    int s = sub[b];
    int r = rel[b];
    for (int d = threadIdx.x; d < EMBED_DIM; d += blockDim.x) {
        g_obj[b * EMBED_DIM + d] = ent[s * EMBED_DIM + d] + relE[r * EMBED_DIM + d];
    }
}

// Persistent work-stealing GEMM-style kernel.
// Work unit: 64(b) x 128(n) tile, processed by a 128-thread CTA with an
// 8x8 register micro-tile (round-2 body: measured ~82% fma on loaded SMs).
// Grid = 444 CTAs (exactly 3/SM) pulling the 456 tiles from an atomic queue
// -> per-SM load self-balances (was the 1.30x static-placement loss).
__global__ __launch_bounds__(128, 3)
void score_kernel(const float* __restrict__ ent, float* __restrict__ out) {
    __shared__ __align__(16) float obj_s[2][8][68];    // [buf][k][b-col]
    __shared__ __align__(16) float ent_s[2][8][132];   // [buf][k][n-col]
    __shared__ int s_tile;

    const int t  = threadIdx.x;
    const int ng = t & 15;   // n-group (0..15)
    const int bg = t >> 4;   // b-group (0..7)

    // loader roles
    const int orow  = t >> 1;   // obj row 0..63
    const int opart = t & 1;    // which float4 of the 8-dim chunk
    const int kb    = opart * 4;

    for (;;) {
        if (t == 0) s_tile = (int)atomicAdd(&g_tile_counter, 1u);
        __syncthreads();
        const int tile = s_tile;
        if (tile >= NUM_TILES) break;

        const int b0 = (tile & 3) * 64;          // b fast: 4 consecutive grabs
        const int n0 = (tile >> 2) * 128;        // share one ent n-tile in L2

        const size_t erow = (size_t)min(n0 + t, NUM_ENT - 1);
        const float* obj_src = &g_obj[(b0 + orow) * EMBED_DIM + opart * 4];
        const float* ent_src = &ent[erow * EMBED_DIM];

        float acc[8][8];
#pragma unroll
        for (int i = 0; i < 8; i++)
#pragma unroll
            for (int j = 0; j < 8; j++) acc[i][j] = 0.0f;

        // ---- load chunk 0 into buffer 0 ----
        {
            float4 ov  = *(const float4*)(obj_src + 0);
            float4 ev0 = *(const float4*)(ent_src + 0);
            float4 ev1 = *(const float4*)(ent_src + 4);
            obj_s[0][kb + 0][orow] = ov.x;
            obj_s[0][kb + 1][orow] = ov.y;
            obj_s[0][kb + 2][orow] = ov.z;
            obj_s[0][kb + 3][orow] = ov.w;
            ent_s[0][0][t] = ev0.x; ent_s[0][1][t] = ev0.y;
            ent_s[0][2][t] = ev0.z; ent_s[0][3][t] = ev0.w;
            ent_s[0][4][t] = ev1.x; ent_s[0][5][t] = ev1.y;
            ent_s[0][6][t] = ev1.z; ent_s[0][7][t] = ev1.w;
        }
        __syncthreads();

        const int NITER = EMBED_DIM / 8;  // 25
#pragma unroll 1
        for (int it = 0; it < NITER; ++it) {
            const int cur = it & 1;

            // prefetch next K-chunk (global -> regs), overlapped with compute
            float4 pov, pev0, pev1;
            const bool have_next = (it + 1 < NITER);
            if (have_next) {
                const int kk = (it + 1) * 8;
                pov  = *(const float4*)(obj_src + kk);
                pev0 = *(const float4*)(ent_src + kk);
                pev1 = *(const float4*)(ent_src + kk + 4);
            }

#pragma unroll
            for (int k = 0; k < 8; ++k) {
                float4 a0 = *(const float4*)&obj_s[cur][k][bg * 4];
                float4 a1 = *(const float4*)&obj_s[cur][k][32 + bg * 4];
                float4 c0 = *(const float4*)&ent_s[cur][k][ng * 4];
                float4 c1 = *(const float4*)&ent_s[cur][k][64 + ng * 4];
                float av[8] = {a0.x, a0.y, a0.z, a0.w, a1.x, a1.y, a1.z, a1.w};
                float bv[8] = {c0.x, c0.y, c0.z, c0.w, c1.x, c1.y, c1.z, c1.w};
#pragma unroll
                for (int i = 0; i < 8; i++)
#pragma unroll
                    for (int j = 0; j < 8; j++)
                        acc[i][j] += fabsf(av[i] - bv[j]);
            }

            if (have_next) {
                const int nxt = cur ^ 1;
                obj_s[nxt][kb + 0][orow] = pov.x;
                obj_s[nxt][kb + 1][orow] = pov.y;
                obj_s[nxt][kb + 2][orow] = pov.z;
                obj_s[nxt][kb + 3][orow] = pov.w;
                ent_s[nxt][0][t] = pev0.x; ent_s[nxt][1][t] = pev0.y;
                ent_s[nxt][2][t] = pev0.z; ent_s[nxt][3][t] = pev0.w;
                ent_s[nxt][4][t] = pev1.x; ent_s[nxt][5][t] = pev1.y;
                ent_s[nxt][6][t] = pev1.z; ent_s[nxt][7][t] = pev1.w;
            }
            __syncthreads();
        }

        // epilogue: score = 1 / (1 + exp(dist - GAMMA))
#pragma unroll
        for (int i = 0; i < 8; ++i) {
            const int b = b0 + bg * 4 + (i & 3) + 32 * (i >> 2);
            const size_t rowoff = (size_t)b * NUM_ENT;
#pragma unroll
            for (int j = 0; j < 8; ++j) {
                const int n = n0 + ng * 4 + (j & 3) + 64 * (j >> 2);
                if (n < NUM_ENT) {
                    out[rowoff + n] = 1.0f / (1.0f + __expf(acc[i][j] - GAMMA));
                }
            }
        }
        // no sync needed here: next iteration's s_tile write is followed by a
        // __syncthreads before anyone reads it, and smem buffers were last
        // read before the final loop barrier above.
    }
}

extern "C" void kernel_launch(void* const* d_in, const int* in_sizes, int n_in,
                              void* d_out, int out_size) {
    const float* ent  = (const float*)d_in[0];   // [14541, 200]
    const float* relE = (const float*)d_in[1];   // [474, 200]
    const int*   sub  = (const int*)d_in[2];     // [256]
    const int*   rel  = (const int*)d_in[3];     // [256]
    // d_in[4] = neg_ents: unused by the reference
    float* out = (float*)d_out;                  // [256, 14541]

    obj_kernel<<<BATCH, 128>>>(ent, relE, sub, rel);
    score_kernel<<<GRID_CTAS, 128>>>(ent, out);
}

// round 11
// speedup vs baseline: 1.2523x; 1.2523x over previous
#include <cuda_runtime.h>
#include <cuda_bf16.h>
#include <math.h>

#define NUM_ENT 14541
#define EMBED_DIM 200
#define BATCH 256
#define GAMMA 9.0f

// Scratch for obj = ent[sub] + rel[rel]  (256 x 200 fp32 = 200 KB)
__device__ float g_obj[BATCH * EMBED_DIM];

__global__ void obj_kernel(const float* __restrict__ ent,
                           const float* __restrict__ relE,
                           const int* __restrict__ sub,
                           const int* __restrict__ rel) {
    int b = blockIdx.x;
    int s = sub[b];
    int r = rel[b];
    for (int d = threadIdx.x; d < EMBED_DIM; d += blockDim.x) {
        g_obj[b * EMBED_DIM + d] = ent[s * EMBED_DIM + d] + relE[r * EMBED_DIM + d];
    }
}

// Tile: 64(b) x 64(n) per block, 128 threads, 8x4 register micro-tile.
// Round-2 body structure (double-buffered smem, transposed [k][col], natural
// K-loop so the compiler unrolls x2 and erases the buffer index).
// Grid = 912 CTAs at occ 4 -> 1.54 waves; wave-2 HW work-stealing balances SMs.
__global__ __launch_bounds__(128, 4)
void score_kernel(const float* __restrict__ ent, float* __restrict__ out) {
    __shared__ __align__(16) float obj_s[2][8][68];   // [buf][k][b-col]
    __shared__ __align__(16) float ent_s[2][8][68];   // [buf][k][n-col]

    const int b0 = blockIdx.x * 64;
    const int n0 = blockIdx.y * 64;
    const int t  = threadIdx.x;
    const int ng = t & 15;   // n-group (0..15), 4 cols each
    const int bg = t >> 4;   // b-group (0..7), 8 rows (4 + 4 at +32)

    // loader roles: thread t handles row t>>1, float4 part t&1 (both tiles)
    const int lrow  = t >> 1;
    const int lpart = t & 1;
    const int kb    = lpart * 4;

    const size_t erow = (size_t)min(n0 + lrow, NUM_ENT - 1);
    const float* obj_src = &g_obj[(b0 + lrow) * EMBED_DIM + lpart * 4];
    const float* ent_src = &ent[erow * EMBED_DIM + lpart * 4];

    float acc[8][4];
#pragma unroll
    for (int i = 0; i < 8; i++)
#pragma unroll
        for (int j = 0; j < 4; j++) acc[i][j] = 0.0f;

    // ---- prefetch + store tile 0 ----
    {
        float4 ov = *(const float4*)(obj_src + 0);
        float4 ev = *(const float4*)(ent_src + 0);
        obj_s[0][kb + 0][lrow] = ov.x;
        obj_s[0][kb + 1][lrow] = ov.y;
        obj_s[0][kb + 2][lrow] = ov.z;
        obj_s[0][kb + 3][lrow] = ov.w;
        ent_s[0][kb + 0][lrow] = ev.x;
        ent_s[0][kb + 1][lrow] = ev.y;
        ent_s[0][kb + 2][lrow] = ev.z;
        ent_s[0][kb + 3][lrow] = ev.w;
    }
    __syncthreads();

    const int NITER = EMBED_DIM / 8;  // 25
    for (int it = 0; it < NITER; ++it) {
        const int cur = it & 1;

        // prefetch next K-chunk (global -> regs), overlapped with compute
        float4 pov, pev;
        const bool have_next = (it + 1 < NITER);
        if (have_next) {
            const int kk = (it + 1) * 8;
            pov = *(const float4*)(obj_src + kk);
            pev = *(const float4*)(ent_src + kk);
        }

#pragma unroll
        for (int k = 0; k < 8; ++k) {
            float4 a0 = *(const float4*)&obj_s[cur][k][bg * 4];
            float4 a1 = *(const float4*)&obj_s[cur][k][32 + bg * 4];
            float4 c0 = *(const float4*)&ent_s[cur][k][ng * 4];
            float av[8] = {a0.x, a0.y, a0.z, a0.w, a1.x, a1.y, a1.z, a1.w};
            float bv[4] = {c0.x, c0.y, c0.z, c0.w};
#pragma unroll
            for (int i = 0; i < 8; i++)
#pragma unroll
                for (int j = 0; j < 4; j++)
                    acc[i][j] += fabsf(av[i] - bv[j]);
        }

        if (have_next) {
            const int nxt = cur ^ 1;
            obj_s[nxt][kb + 0][lrow] = pov.x;
            obj_s[nxt][kb + 1][lrow] = pov.y;
            obj_s[nxt][kb + 2][lrow] = pov.z;
            obj_s[nxt][kb + 3][lrow] = pov.w;
            ent_s[nxt][kb + 0][lrow] = pev.x;
            ent_s[nxt][kb + 1][lrow] = pev.y;
            ent_s[nxt][kb + 2][lrow] = pev.z;
            ent_s[nxt][kb + 3][lrow] = pev.w;
        }
        __syncthreads();
    }

    // epilogue: score = 1 / (1 + exp(dist - GAMMA))
#pragma unroll
    for (int i = 0; i < 8; ++i) {
        const int b = b0 + bg * 4 + (i & 3) + 32 * (i >> 2);
        const size_t rowoff = (size_t)b * NUM_ENT;
#pragma unroll
        for (int j = 0; j < 4; ++j) {
            const int n = n0 + ng * 4 + j;
            if (n < NUM_ENT) {
                out[rowoff + n] = 1.0f / (1.0f + __expf(acc[i][j] - GAMMA));
            }
        }
    }
}

extern "C" void kernel_launch(void* const* d_in, const int* in_sizes, int n_in,
                              void* d_out, int out_size) {
    const float* ent  = (const float*)d_in[0];   // [14541, 200]
    const float* relE = (const float*)d_in[1];   // [474, 200]
    const int*   sub  = (const int*)d_in[2];     // [256]
    const int*   rel  = (const int*)d_in[3];     // [256]
    // d_in[4] = neg_ents: unused by the reference
    float* out = (float*)d_out;                  // [256, 14541]

    obj_kernel<<<BATCH, 128>>>(ent, relE, sub, rel);

    // x = b-tile (fast): 4 consecutive bids reuse one ent n-tile in L2
    dim3 grid(BATCH / 64, (NUM_ENT + 63) / 64);  // (4, 228) = 912 CTAs
    score_kernel<<<grid, 128>>>(ent, out);
}